// round 4
// baseline (speedup 1.0000x reference)
#include <cuda_runtime.h>
#include <cstdint>

#define LRELU_ALPHA 0.2f

typedef unsigned long long u64;

// packed f32x2 helpers (sm_103a FFMA2 is PTX-only)
__device__ __forceinline__ void ffma2(u64 &d, u64 a, u64 b){
    asm("fma.rn.f32x2 %0, %1, %2, %0;" : "+l"(d) : "l"(a), "l"(b));
}
__device__ __forceinline__ u64 pack2(float s){
    u64 d; asm("mov.b64 %0, {%1, %1};" : "=l"(d) : "f"(s)); return d;
}
__device__ __forceinline__ void unpack2(float &lo, float &hi, u64 v){
    asm("mov.b64 {%0,%1}, %2;" : "=f"(lo), "=f"(hi) : "l"(v));
}

// ping-pong activation buffers (allocation-free scratch)
__device__ __align__(16) float g_bufA[67108864];   // h1, h3, d1, d3
__device__ __align__(16) float g_bufB[33554432];   // h2, q,  d2

// ---------------------------------------------------------------------------
// Shared-memory-staged conv / transposed-conv, NHWC fp32, w in HWIO [9][CI][CO].
// Input rows staged in smem as 8B DUP-PAIRS (v,v): the f32x2 broadcast happens
// once per element at staging time -> zero MOVs in the hot loop.
//   conv   stride S (SAME, pad_lo=0): DIL=1, PAD=0, rows [S*h0, S*(h0+HR-1)+2]
//   deconv stride 2 (lhs_dil=2,pad=(2,1)): S=1, DIL=2, PAD=2, rows [h0/2-1 ..]
// Thread = 4 consecutive couts x RP consecutive output columns, HR rows loop.
// ---------------------------------------------------------------------------
template<int S, int DIL, int PAD, int CI, int CO, int RP, int HR, int NR, bool RELU>
__global__ __launch_bounds__(256) void convS_kernel(
    const float* __restrict__ in, const float* __restrict__ w,
    const float* __restrict__ bias, float* __restrict__ out,
    int N, int Hin, int Win, int Hout, int Wout)
{
    extern __shared__ u64 sx[];            // [NR][Win][CI+1] dup-pairs
    constexpr int CIP = CI + 1;            // odd 8B-stride -> conflict-free
    constexpr int CQ  = CO / 4;
    constexpr int G   = 256 / CQ;
    static_assert(RP % 2 == 0, "RP even for compile-time phase folding");

    const int cq = threadIdx.x % CQ;
    const int g  = threadIdx.x / CQ;
    const int w0 = (blockIdx.x * G + g) * RP;
    const int h0 = blockIdx.y * HR;
    const int n  = blockIdx.z;
    const int row_min = (DIL==2) ? (h0/2 - 1) : (h0*S);

    // ---- stage input rows as dup-pairs ----
    {
        const int total = NR * Win * CI;
        for (int idx = threadIdx.x * 4; idx < total; idx += 256 * 4){
            int ci = idx % CI; int t = idx / CI; int iw = t % Win; int lr = t / Win;
            int ihy = row_min + lr;
            if (ihy >= 0 && ihy < Hin){
                float4 v = *reinterpret_cast<const float4*>(
                    in + ((size_t)(n*Hin + ihy)*Win + iw)*CI + ci);
                u64* dst = sx + ((size_t)lr*Win + iw)*CIP + ci;
                dst[0]=pack2(v.x); dst[1]=pack2(v.y); dst[2]=pack2(v.z); dst[3]=pack2(v.w);
            }
        }
    }
    __syncthreads();

    const float4 bv = *reinterpret_cast<const float4*>(bias + 4*cq);

    for (int hr = 0; hr < HR; hr++){
        const int h = h0 + hr;

        u64 acc0[RP], acc1[RP];
        #pragma unroll
        for (int r=0;r<RP;r++){ acc0[r]=0ull; acc1[r]=0ull; }

        #pragma unroll
        for (int ky=0; ky<3; ky++){
            int uy = h*S + ky - PAD;
            int ihy;
            if (DIL==2){ if (uy & 1) continue; ihy = uy >> 1; } else { ihy = uy; }
            if (ihy < 0 || ihy >= Hin) continue;
            const u64* __restrict__ rowp = sx + (size_t)(ihy - row_min)*Win*CIP;

            #pragma unroll
            for (int kx=0; kx<3; kx++){
                const float* __restrict__ wp = w + (size_t)((ky*3+kx)*CI)*CO + 4*cq;
                int  ofs[RP];
                bool v[RP];
                #pragma unroll
                for (int r=0;r<RP;r++){
                    bool phase = (DIL==1) || (((r + kx - PAD) & 1) == 0);
                    int ux = (w0+r)*S + kx - PAD;
                    int iw = (DIL==2) ? (ux >> 1) : ux;
                    v[r]   = phase && (iw >= 0) && (iw < Win);
                    ofs[r] = v[r] ? iw*CIP : 0;
                }

                #pragma unroll 2
                for (int ci=0; ci<CI; ci+=4){
                    ulonglong2 wv0 = *reinterpret_cast<const ulonglong2*>(wp + (size_t)(ci+0)*CO);
                    ulonglong2 wv1 = *reinterpret_cast<const ulonglong2*>(wp + (size_t)(ci+1)*CO);
                    ulonglong2 wv2 = *reinterpret_cast<const ulonglong2*>(wp + (size_t)(ci+2)*CO);
                    ulonglong2 wv3 = *reinterpret_cast<const ulonglong2*>(wp + (size_t)(ci+3)*CO);
                    #pragma unroll
                    for (int r=0;r<RP;r++){
                        if ((DIL==1) || (((r + kx - PAD) & 1) == 0)){
                            if (v[r]){
                                const u64* xp = rowp + ofs[r] + ci;
                                u64 x0 = xp[0], x1 = xp[1], x2 = xp[2], x3 = xp[3];
                                ffma2(acc0[r], wv0.x, x0); ffma2(acc1[r], wv0.y, x0);
                                ffma2(acc0[r], wv1.x, x1); ffma2(acc1[r], wv1.y, x1);
                                ffma2(acc0[r], wv2.x, x2); ffma2(acc1[r], wv2.y, x2);
                                ffma2(acc0[r], wv3.x, x3); ffma2(acc1[r], wv3.y, x3);
                            }
                        }
                    }
                }
            }
        }

        const size_t ob = ((size_t)(n*Hout + h)*Wout + w0)*CO + 4*cq;
        #pragma unroll
        for (int r=0;r<RP;r++){
            float a0,a1,a2,a3;
            unpack2(a0,a1,acc0[r]); unpack2(a2,a3,acc1[r]);
            a0 += bv.x; a1 += bv.y; a2 += bv.z; a3 += bv.w;
            if (RELU){
                a0 = (a0 > 0.f) ? a0 : LRELU_ALPHA * a0;
                a1 = (a1 > 0.f) ? a1 : LRELU_ALPHA * a1;
                a2 = (a2 > 0.f) ? a2 : LRELU_ALPHA * a2;
                a3 = (a3 > 0.f) ? a3 : LRELU_ALPHA * a3;
            }
            float4 o; o.x=a0; o.y=a1; o.z=a2; o.w=a3;
            *reinterpret_cast<float4*>(out + ob + (size_t)r*CO) = o;
        }
    }
}

// ---------------------------------------------------------------------------
// enc1 (CI=3): R3-style kernel, scalar x path (tiny layer)
// ---------------------------------------------------------------------------
template<int CI, int CO, int RP>
__global__ __launch_bounds__(256) void conv4_kernel(
    const float* __restrict__ in, const float* __restrict__ w,
    const float* __restrict__ bias, float* __restrict__ out,
    int N, int Hin, int Win, int Hout, int Wout)
{
    constexpr int CQ = CO / 4;
    constexpr int G  = 256 / CQ;
    const int cq = threadIdx.x % CQ;
    const int g  = threadIdx.x / CQ;
    const int w0 = (blockIdx.x * G + g) * RP;
    const int h  = blockIdx.y;
    const int n  = blockIdx.z;
    if (w0 >= Wout) return;

    u64 acc0[RP], acc1[RP];
    #pragma unroll
    for (int r=0;r<RP;r++){ acc0[r]=0ull; acc1[r]=0ull; }

    #pragma unroll
    for (int ky=0; ky<3; ky++){
        int ihy = h*2 + ky;
        if (ihy >= Hin) continue;
        const float* __restrict__ rowp = in + (size_t)(n*Hin + ihy) * Win * CI;
        #pragma unroll
        for (int kx=0; kx<3; kx++){
            const float* __restrict__ wp = w + (size_t)((ky*3+kx)*CI) * CO + 4*cq;
            #pragma unroll
            for (int ci=0; ci<CI; ci++){
                ulonglong2 wv = *reinterpret_cast<const ulonglong2*>(wp + (size_t)ci*CO);
                #pragma unroll
                for (int r=0;r<RP;r++){
                    int iw = (w0+r)*2 + kx;
                    if (iw < Win){
                        u64 p = pack2(rowp[(size_t)iw*CI + ci]);
                        ffma2(acc0[r], wv.x, p);
                        ffma2(acc1[r], wv.y, p);
                    }
                }
            }
        }
    }

    const float4 bv = *reinterpret_cast<const float4*>(bias + 4*cq);
    const size_t ob = ((size_t)(n*Hout + h)*Wout + w0)*CO + 4*cq;
    #pragma unroll
    for (int r=0;r<RP;r++){
        float a0,a1,a2,a3;
        unpack2(a0,a1,acc0[r]); unpack2(a2,a3,acc1[r]);
        a0 += bv.x; a1 += bv.y; a2 += bv.z; a3 += bv.w;
        a0 = (a0 > 0.f) ? a0 : LRELU_ALPHA * a0;
        a1 = (a1 > 0.f) ? a1 : LRELU_ALPHA * a1;
        a2 = (a2 > 0.f) ? a2 : LRELU_ALPHA * a2;
        a3 = (a3 > 0.f) ? a3 : LRELU_ALPHA * a3;
        float4 o; o.x=a0; o.y=a1; o.z=a2; o.w=a3;
        *reinterpret_cast<float4*>(out + ob + (size_t)r*CO) = o;
    }
}

// ---------------------------------------------------------------------------
// fused enc4 (1x1 conv, 64->32) + vector quantization
// ---------------------------------------------------------------------------
__global__ __launch_bounds__(128, 2) void enc4_vq_kernel(
    const float* __restrict__ h3, const float* __restrict__ w,
    const float* __restrict__ b, const float* __restrict__ cb,
    float* __restrict__ q, int NP)
{
    __shared__ float sw[2048];   // w  [64][32]
    __shared__ float scb[2048];  // cb [32][64]
    for (int i = threadIdx.x; i < 2048; i += 128){ sw[i] = w[i]; scb[i] = cb[i]; }
    __syncthreads();

    int p = blockIdx.x*blockDim.x + threadIdx.x;
    if (p >= NP) return;
    float z[32];
    #pragma unroll
    for (int d=0;d<32;d++) z[d] = b[d];
    const float* hp = h3 + (size_t)p*64;
    #pragma unroll
    for (int c4=0;c4<64;c4+=4){
        float4 hv = *reinterpret_cast<const float4*>(hp + c4);
        #pragma unroll
        for (int d=0;d<32;d++){
            z[d] += hv.x * sw[(c4+0)*32 + d];
            z[d] += hv.y * sw[(c4+1)*32 + d];
            z[d] += hv.z * sw[(c4+2)*32 + d];
            z[d] += hv.w * sw[(c4+3)*32 + d];
        }
    }
    float best = 3.4e38f; int bk = 0;
    for (int k=0;k<64;k++){
        float dist = 0.f;
        #pragma unroll
        for (int d=0;d<32;d++){
            float e = scb[d*64 + k];
            dist += e*(e - 2.f*z[d]);
        }
        if (dist < best){ best = dist; bk = k; }   // strict < == first-min (jnp.argmin)
    }
    float* qp = q + (size_t)p*32;
    #pragma unroll
    for (int d=0;d<32;d++) qp[d] = scb[d*64 + bk];
}

// ---------------------------------------------------------------------------
// dec4: conv_transpose stride 1 (== SAME conv pad 1), CI=32, CO=1.
// ---------------------------------------------------------------------------
__global__ __launch_bounds__(256) void dec4_kernel(
    const float* __restrict__ in, const float* __restrict__ w,
    const float* __restrict__ b, float* __restrict__ out,
    int N, int H, int W)
{
    int gw = (blockIdx.x * blockDim.x + threadIdx.x) >> 5;
    int lane = threadIdx.x & 31;
    int gpr = W >> 2;
    int total = N*H*gpr;
    if (gw >= total) return;
    int gx = gw % gpr; int t = gw / gpr;
    int h = t % H; int n = t / H;
    int w0 = gx*4;

    float wk[9];
    #pragma unroll
    for (int i=0;i<9;i++) wk[i] = w[i*32 + lane];

    float acc[4] = {0.f,0.f,0.f,0.f};
    #pragma unroll
    for (int ky=0;ky<3;ky++){
        int ih = h + ky - 1;
        if (ih < 0 || ih >= H) continue;
        const float* rowp = in + ((size_t)(n*H + ih)*W)*32 + lane;
        float v[6];
        #pragma unroll
        for (int c=0;c<6;c++){
            int iw = w0 - 1 + c;
            v[c] = (iw >= 0 && iw < W) ? rowp[(size_t)iw*32] : 0.f;
        }
        #pragma unroll
        for (int kx=0;kx<3;kx++)
            #pragma unroll
            for (int r=0;r<4;r++)
                acc[r] += v[r+kx] * wk[ky*3+kx];
    }
    float bv = b[0];
    #pragma unroll
    for (int r=0;r<4;r++){
        float a = acc[r];
        #pragma unroll
        for (int o=16;o;o>>=1) a += __shfl_xor_sync(0xffffffffu, a, o);
        if (lane == 0) out[((size_t)(n*H + h)*W) + w0 + r] = a + bv;
    }
}

extern "C" void kernel_launch(void* const* d_in, const int* in_sizes, int n_in,
                              void* d_out, int out_size)
{
    (void)in_sizes; (void)n_in; (void)out_size;
    const float* x   = (const float*)d_in[0];
    const float* e1w = (const float*)d_in[1];  const float* e1b = (const float*)d_in[2];
    const float* e2w = (const float*)d_in[3];  const float* e2b = (const float*)d_in[4];
    const float* e3w = (const float*)d_in[5];  const float* e3b = (const float*)d_in[6];
    const float* e4w = (const float*)d_in[7];  const float* e4b = (const float*)d_in[8];
    const float* cb  = (const float*)d_in[9];
    const float* d1w = (const float*)d_in[10]; const float* d1b = (const float*)d_in[11];
    const float* d2w = (const float*)d_in[12]; const float* d2b = (const float*)d_in[13];
    const float* d3w = (const float*)d_in[14]; const float* d3b = (const float*)d_in[15];
    const float* d4w = (const float*)d_in[16]; const float* d4b = (const float*)d_in[17];
    float* out = (float*)d_out;

    float *A, *B;
    cudaGetSymbolAddress((void**)&A, g_bufA);
    cudaGetSymbolAddress((void**)&B, g_bufB);

    // smem sizes: NR * Win * (CI+1) * 8 bytes
    auto enc2 = convS_kernel<2,1,0,32,64,2,2,5,true>;   // 5*128*33*8 = 168960
    auto enc3 = convS_kernel<2,1,0,64,64,2,2,5,true>;   // 5* 64*65*8 = 166400
    auto dec1 = convS_kernel<1,2,2,32,64,4,4,3,true>;   // 3* 32*33*8 =  25344
    auto dec2 = convS_kernel<1,2,2,64,64,8,4,3,true>;   // 3* 64*65*8 =  99840
    auto dec3 = convS_kernel<1,2,2,64,32,8,4,3,true>;   // 3*128*65*8 = 199680
    cudaFuncSetAttribute(enc2, cudaFuncAttributeMaxDynamicSharedMemorySize, 168960);
    cudaFuncSetAttribute(enc3, cudaFuncAttributeMaxDynamicSharedMemorySize, 166400);
    cudaFuncSetAttribute(dec2, cudaFuncAttributeMaxDynamicSharedMemorySize,  99840);
    cudaFuncSetAttribute(dec3, cudaFuncAttributeMaxDynamicSharedMemorySize, 199680);

    // encoder: 256 -> 128 -> 64 -> 32
    conv4_kernel<3,32,4><<< dim3(1,128,32), 256 >>>(x, e1w, e1b, A, 32,256,256,128,128);
    enc2<<< dim3(2,32,32), 256, 168960 >>>(A, e2w, e2b, B, 32,128,128, 64, 64);
    enc3<<< dim3(1,16,32), 256, 166400 >>>(B, e3w, e3b, A, 32, 64, 64, 32, 32);

    // enc4 (1x1) + VQ fused
    enc4_vq_kernel<<< 256, 128 >>>(A, e4w, e4b, cb, B, 32768);

    // decoder: 32 -> 64 -> 128 -> 256
    dec1<<< dim3(1,16,32), 256,  25344 >>>(B, d1w, d1b, A, 32, 32, 32, 64, 64);
    dec2<<< dim3(1,32,32), 256,  99840 >>>(A, d2w, d2b, B, 32, 64, 64,128,128);
    dec3<<< dim3(1,64,32), 256, 199680 >>>(B, d3w, d3b, A, 32,128,128,256,256);

    // dec4: stride-1 deconv == SAME conv, CO=1
    dec4_kernel<<< 65536, 256 >>>(A, d4w, d4b, out, 32, 256, 256);
}

// round 5
// speedup vs baseline: 1.7513x; 1.7513x over previous
#include <cuda_runtime.h>
#include <cstdint>

#define LRELU_ALPHA 0.2f

typedef unsigned long long u64;

// packed f32x2 helpers (sm_103a FFMA2 is PTX-only)
__device__ __forceinline__ void ffma2(u64 &d, u64 a, u64 b){
    asm("fma.rn.f32x2 %0, %1, %2, %0;" : "+l"(d) : "l"(a), "l"(b));
}
__device__ __forceinline__ u64 pack2(float s){
    u64 d; asm("mov.b64 %0, {%1, %1};" : "=l"(d) : "f"(s)); return d;
}
__device__ __forceinline__ void unpack2(float &lo, float &hi, u64 v){
    asm("mov.b64 {%0,%1}, %2;" : "=f"(lo), "=f"(hi) : "l"(v));
}

// ping-pong activation buffers (allocation-free scratch)
__device__ __align__(16) float g_bufA[67108864];   // h1, h3, d1, d3
__device__ __align__(16) float g_bufB[33554432];   // h2, q,  d2

// ---------------------------------------------------------------------------
// 3x3 conv / transposed-conv, NHWC fp32, weights in HWIO [9][CI][CO].
//   conv   stride S (SAME, pad_lo=0): DIL=1, PAD=0
//   deconv stride 2 (lhs_dilation=2, pad=(2,1)): S=1, DIL=2, PAD=2
// Thread = NC consecutive couts x RP consecutive output columns.
// Block = 256 threads tiling (Wout/RP groups) x HB rows exactly.
// kx outer so per-r offset/phase math is computed once per kx (3x not 9x).
// ---------------------------------------------------------------------------
template<int S, int DIL, int PAD, int CI, int CO, int NC, int RP, int HB>
__global__ __launch_bounds__(256) void convN_kernel(
    const float* __restrict__ in, const float* __restrict__ w,
    const float* __restrict__ bias, float* __restrict__ out,
    int N, int Hin, int Win, int Hout, int Wout)
{
    constexpr int CQ = CO / NC;        // cout groups
    constexpr int G  = 256 / CQ;       // pixel groups per block
    constexpr int WG = G / HB;         // column groups per row
    constexpr int NJ = NC / 4;         // float4 weight words per ci
    static_assert(RP % 2 == 0, "RP even for compile-time phase folding");

    const int cq = threadIdx.x % CQ;
    const int g  = threadIdx.x / CQ;
    const int wg = g % WG;
    const int hl = g / WG;
    const int w0 = wg * RP;            // WG*RP == Wout by construction
    const int h  = blockIdx.y * HB + hl;
    const int n  = blockIdx.z;

    u64 acc[RP][NC/2];
    #pragma unroll
    for (int r=0;r<RP;r++)
        #pragma unroll
        for (int k=0;k<NC/2;k++) acc[r][k] = 0ull;

    #pragma unroll
    for (int kx=0; kx<3; kx++){
        // per-column offsets/validity: computed once per kx
        int  ofs[RP];
        bool v[RP];
        #pragma unroll
        for (int r=0;r<RP;r++){
            bool phase = (DIL==1) || (((r + kx - PAD) & 1) == 0);
            int ux = (w0+r)*S + kx - PAD;
            int iw = (DIL==2) ? (ux >> 1) : ux;
            v[r]   = phase && (iw >= 0) && (iw < Win);
            ofs[r] = v[r] ? iw*CI : 0;
        }

        #pragma unroll
        for (int ky=0; ky<3; ky++){
            int uy = h*S + ky - PAD;
            int ihy;
            if (DIL==2){ if (uy & 1) continue; ihy = uy >> 1; } else { ihy = uy; }
            if (ihy < 0 || ihy >= Hin) continue;
            const float* __restrict__ rowp = in + (size_t)(n*Hin + ihy) * Win * CI;
            const float* __restrict__ wp   = w + (size_t)((ky*3+kx)*CI)*CO + NC*cq;

            #pragma unroll 2
            for (int ci=0; ci<CI; ci+=4){
                ulonglong2 wv[4][NJ];
                #pragma unroll
                for (int c4=0;c4<4;c4++)
                    #pragma unroll
                    for (int j=0;j<NJ;j++)
                        wv[c4][j] = *reinterpret_cast<const ulonglong2*>(
                            wp + (size_t)(ci+c4)*CO + 4*j);

                #pragma unroll
                for (int r=0;r<RP;r++){
                    if ((DIL==1) || (((r + kx - PAD) & 1) == 0)){
                        if (v[r]){
                            float4 xv = *reinterpret_cast<const float4*>(rowp + ofs[r] + ci);
                            u64 p0 = pack2(xv.x), p1 = pack2(xv.y);
                            u64 p2 = pack2(xv.z), p3 = pack2(xv.w);
                            #pragma unroll
                            for (int j=0;j<NJ;j++){
                                ffma2(acc[r][2*j],   wv[0][j].x, p0);
                                ffma2(acc[r][2*j+1], wv[0][j].y, p0);
                                ffma2(acc[r][2*j],   wv[1][j].x, p1);
                                ffma2(acc[r][2*j+1], wv[1][j].y, p1);
                                ffma2(acc[r][2*j],   wv[2][j].x, p2);
                                ffma2(acc[r][2*j+1], wv[2][j].y, p2);
                                ffma2(acc[r][2*j],   wv[3][j].x, p3);
                                ffma2(acc[r][2*j+1], wv[3][j].y, p3);
                            }
                        }
                    }
                }
            }
        }
    }

    float4 bvv[NJ];
    #pragma unroll
    for (int j=0;j<NJ;j++)
        bvv[j] = *reinterpret_cast<const float4*>(bias + NC*cq + 4*j);

    const size_t ob = ((size_t)(n*Hout + h)*Wout + w0)*CO + NC*cq;
    #pragma unroll
    for (int r=0;r<RP;r++){
        #pragma unroll
        for (int j=0;j<NJ;j++){
            float a0,a1,a2,a3;
            unpack2(a0,a1,acc[r][2*j]); unpack2(a2,a3,acc[r][2*j+1]);
            a0 += bvv[j].x; a1 += bvv[j].y; a2 += bvv[j].z; a3 += bvv[j].w;
            a0 = (a0 > 0.f) ? a0 : LRELU_ALPHA * a0;
            a1 = (a1 > 0.f) ? a1 : LRELU_ALPHA * a1;
            a2 = (a2 > 0.f) ? a2 : LRELU_ALPHA * a2;
            a3 = (a3 > 0.f) ? a3 : LRELU_ALPHA * a3;
            float4 o; o.x=a0; o.y=a1; o.z=a2; o.w=a3;
            *reinterpret_cast<float4*>(out + ob + (size_t)r*CO + 4*j) = o;
        }
    }
}

// ---------------------------------------------------------------------------
// enc1 (CI=3, stride 2): scalar x path (tiny layer)
// ---------------------------------------------------------------------------
template<int CI, int CO, int RP>
__global__ __launch_bounds__(256) void conv4_kernel(
    const float* __restrict__ in, const float* __restrict__ w,
    const float* __restrict__ bias, float* __restrict__ out,
    int N, int Hin, int Win, int Hout, int Wout)
{
    constexpr int CQ = CO / 4;
    constexpr int G  = 256 / CQ;
    const int cq = threadIdx.x % CQ;
    const int g  = threadIdx.x / CQ;
    const int w0 = (blockIdx.x * G + g) * RP;
    const int h  = blockIdx.y;
    const int n  = blockIdx.z;
    if (w0 >= Wout) return;

    u64 acc0[RP], acc1[RP];
    #pragma unroll
    for (int r=0;r<RP;r++){ acc0[r]=0ull; acc1[r]=0ull; }

    #pragma unroll
    for (int ky=0; ky<3; ky++){
        int ihy = h*2 + ky;
        if (ihy >= Hin) continue;
        const float* __restrict__ rowp = in + (size_t)(n*Hin + ihy) * Win * CI;
        #pragma unroll
        for (int kx=0; kx<3; kx++){
            const float* __restrict__ wp = w + (size_t)((ky*3+kx)*CI) * CO + 4*cq;
            #pragma unroll
            for (int ci=0; ci<CI; ci++){
                ulonglong2 wv = *reinterpret_cast<const ulonglong2*>(wp + (size_t)ci*CO);
                #pragma unroll
                for (int r=0;r<RP;r++){
                    int iw = (w0+r)*2 + kx;
                    if (iw < Win){
                        u64 p = pack2(rowp[(size_t)iw*CI + ci]);
                        ffma2(acc0[r], wv.x, p);
                        ffma2(acc1[r], wv.y, p);
                    }
                }
            }
        }
    }

    const float4 bv = *reinterpret_cast<const float4*>(bias + 4*cq);
    const size_t ob = ((size_t)(n*Hout + h)*Wout + w0)*CO + 4*cq;
    #pragma unroll
    for (int r=0;r<RP;r++){
        float a0,a1,a2,a3;
        unpack2(a0,a1,acc0[r]); unpack2(a2,a3,acc1[r]);
        a0 += bv.x; a1 += bv.y; a2 += bv.z; a3 += bv.w;
        a0 = (a0 > 0.f) ? a0 : LRELU_ALPHA * a0;
        a1 = (a1 > 0.f) ? a1 : LRELU_ALPHA * a1;
        a2 = (a2 > 0.f) ? a2 : LRELU_ALPHA * a2;
        a3 = (a3 > 0.f) ? a3 : LRELU_ALPHA * a3;
        float4 o; o.x=a0; o.y=a1; o.z=a2; o.w=a3;
        *reinterpret_cast<float4*>(out + ob + (size_t)r*CO) = o;
    }
}

// ---------------------------------------------------------------------------
// fused enc4 (1x1 conv, 64->32) + vector quantization
// ---------------------------------------------------------------------------
__global__ __launch_bounds__(128, 2) void enc4_vq_kernel(
    const float* __restrict__ h3, const float* __restrict__ w,
    const float* __restrict__ b, const float* __restrict__ cb,
    float* __restrict__ q, int NP)
{
    __shared__ float sw[2048];   // w  [64][32]
    __shared__ float scb[2048];  // cb [32][64]
    for (int i = threadIdx.x; i < 2048; i += 128){ sw[i] = w[i]; scb[i] = cb[i]; }
    __syncthreads();

    int p = blockIdx.x*blockDim.x + threadIdx.x;
    if (p >= NP) return;
    float z[32];
    #pragma unroll
    for (int d=0;d<32;d++) z[d] = b[d];
    const float* hp = h3 + (size_t)p*64;
    #pragma unroll
    for (int c4=0;c4<64;c4+=4){
        float4 hv = *reinterpret_cast<const float4*>(hp + c4);
        #pragma unroll
        for (int d=0;d<32;d++){
            z[d] += hv.x * sw[(c4+0)*32 + d];
            z[d] += hv.y * sw[(c4+1)*32 + d];
            z[d] += hv.z * sw[(c4+2)*32 + d];
            z[d] += hv.w * sw[(c4+3)*32 + d];
        }
    }
    float best = 3.4e38f; int bk = 0;
    for (int k=0;k<64;k++){
        float dist = 0.f;
        #pragma unroll
        for (int d=0;d<32;d++){
            float e = scb[d*64 + k];
            dist += e*(e - 2.f*z[d]);
        }
        if (dist < best){ best = dist; bk = k; }   // strict < == first-min (jnp.argmin)
    }
    float* qp = q + (size_t)p*32;
    #pragma unroll
    for (int d=0;d<32;d++) qp[d] = scb[d*64 + bk];
}

// ---------------------------------------------------------------------------
// dec4: conv_transpose stride 1 (== SAME conv pad 1), CI=32, CO=1.
// ---------------------------------------------------------------------------
__global__ __launch_bounds__(256) void dec4_kernel(
    const float* __restrict__ in, const float* __restrict__ w,
    const float* __restrict__ b, float* __restrict__ out,
    int N, int H, int W)
{
    int gw = (blockIdx.x * blockDim.x + threadIdx.x) >> 5;
    int lane = threadIdx.x & 31;
    int gpr = W >> 2;
    int total = N*H*gpr;
    if (gw >= total) return;
    int gx = gw % gpr; int t = gw / gpr;
    int h = t % H; int n = t / H;
    int w0 = gx*4;

    float wk[9];
    #pragma unroll
    for (int i=0;i<9;i++) wk[i] = w[i*32 + lane];

    float acc[4] = {0.f,0.f,0.f,0.f};
    #pragma unroll
    for (int ky=0;ky<3;ky++){
        int ih = h + ky - 1;
        if (ih < 0 || ih >= H) continue;
        const float* rowp = in + ((size_t)(n*H + ih)*W)*32 + lane;
        float v[6];
        #pragma unroll
        for (int c=0;c<6;c++){
            int iw = w0 - 1 + c;
            v[c] = (iw >= 0 && iw < W) ? rowp[(size_t)iw*32] : 0.f;
        }
        #pragma unroll
        for (int kx=0;kx<3;kx++)
            #pragma unroll
            for (int r=0;r<4;r++)
                acc[r] += v[r+kx] * wk[ky*3+kx];
    }
    float bv = b[0];
    #pragma unroll
    for (int r=0;r<4;r++){
        float a = acc[r];
        #pragma unroll
        for (int o=16;o;o>>=1) a += __shfl_xor_sync(0xffffffffu, a, o);
        if (lane == 0) out[((size_t)(n*H + h)*W) + w0 + r] = a + bv;
    }
}

extern "C" void kernel_launch(void* const* d_in, const int* in_sizes, int n_in,
                              void* d_out, int out_size)
{
    (void)in_sizes; (void)n_in; (void)out_size;
    const float* x   = (const float*)d_in[0];
    const float* e1w = (const float*)d_in[1];  const float* e1b = (const float*)d_in[2];
    const float* e2w = (const float*)d_in[3];  const float* e2b = (const float*)d_in[4];
    const float* e3w = (const float*)d_in[5];  const float* e3b = (const float*)d_in[6];
    const float* e4w = (const float*)d_in[7];  const float* e4b = (const float*)d_in[8];
    const float* cb  = (const float*)d_in[9];
    const float* d1w = (const float*)d_in[10]; const float* d1b = (const float*)d_in[11];
    const float* d2w = (const float*)d_in[12]; const float* d2b = (const float*)d_in[13];
    const float* d3w = (const float*)d_in[14]; const float* d3b = (const float*)d_in[15];
    const float* d4w = (const float*)d_in[16]; const float* d4b = (const float*)d_in[17];
    float* out = (float*)d_out;

    float *A, *B;
    cudaGetSymbolAddress((void**)&A, g_bufA);
    cudaGetSymbolAddress((void**)&B, g_bufB);

    // encoder: 256 -> 128 -> 64 -> 32
    // enc1: CI=3 scalar path
    conv4_kernel<3,32,4><<< dim3(1,128,32), 256 >>>(x, e1w, e1b, A, 32,256,256,128,128);
    // enc2: CQ=8,G=32,HB=2,WG=16,RP=4 -> 64 cols
    convN_kernel<2,1,0,32,64,8,4,2><<< dim3(1,32,32), 256 >>>(A, e2w, e2b, B, 32,128,128, 64, 64);
    // enc3: CQ=8,G=32,HB=4,WG=8,RP=4 -> 32 cols
    convN_kernel<2,1,0,64,64,8,4,4><<< dim3(1,8,32), 256 >>>(B, e3w, e3b, A, 32, 64, 64, 32, 32);

    // enc4 (1x1) + VQ fused
    enc4_vq_kernel<<< 256, 128 >>>(A, e4w, e4b, cb, B, 32768);

    // decoder: 32 -> 64 -> 128 -> 256
    // dec1: CQ=8,G=32,HB=4,WG=8,RP=8 -> 64 cols
    convN_kernel<1,2,2,32,64,8,8,4><<< dim3(1,16,32), 256 >>>(B, d1w, d1b, A, 32, 32, 32, 64, 64);
    // dec2: CQ=8,G=32,HB=2,WG=16,RP=8 -> 128 cols
    convN_kernel<1,2,2,64,64,8,8,2><<< dim3(1,64,32), 256 >>>(A, d2w, d2b, B, 32, 64, 64,128,128);
    // dec3: CQ=4,G=64,HB=2,WG=32,RP=8 -> 256 cols
    convN_kernel<1,2,2,64,32,8,8,2><<< dim3(1,128,32), 256 >>>(B, d3w, d3b, A, 32,128,128,256,256);

    // dec4: stride-1 deconv == SAME conv, CO=1
    dec4_kernel<<< 65536, 256 >>>(A, d4w, d4b, out, 32, 256, 256);
}

// round 6
// speedup vs baseline: 2.0648x; 1.1790x over previous
#include <cuda_runtime.h>
#include <cstdint>

#define LRELU_ALPHA 0.2f

typedef unsigned long long u64;

// packed f32x2 helpers (sm_103a FFMA2 is PTX-only)
__device__ __forceinline__ void ffma2(u64 &d, u64 a, u64 b){
    asm("fma.rn.f32x2 %0, %1, %2, %0;" : "+l"(d) : "l"(a), "l"(b));
}
__device__ __forceinline__ u64 pack2(float s){
    u64 d; asm("mov.b64 %0, {%1, %1};" : "=l"(d) : "f"(s)); return d;
}
__device__ __forceinline__ void unpack2(float &lo, float &hi, u64 v){
    asm("mov.b64 {%0,%1}, %2;" : "=f"(lo), "=f"(hi) : "l"(v));
}

// ping-pong activation buffers (allocation-free scratch)
__device__ __align__(16) float g_bufA[67108864];   // h1, h3, d1, d3
__device__ __align__(16) float g_bufB[33554432];   // h2, q,  d2

// ---------------------------------------------------------------------------
// Stride-2 transposed conv (lhs_dilation=2, pad=(2,1)), NHWC, w HWIO [9][CI][CO].
// Thread = 4 couts x 4 output cols x 2 output rows (h0 even, h0+1 odd).
// Input rows: ihyA = h0/2-1 feeds even row (ky=0); ihyB = h0/2 feeds even row
// (ky=2) AND odd row (ky=1) -> x loaded+packed ONCE, used for both rows.
// Needed x cols per chunk: iwb-1, iwb, iwb+1 (iwb = w0/2), 3 LDG.128 only.
// Tap map (w0,r): r0: kx0*x_m1 + kx2*x_0 ; r1: kx1*x_0 ;
//                 r2: kx0*x_0  + kx2*x_p1; r3: kx1*x_p1
// ---------------------------------------------------------------------------
template<int CI, int CO>
__global__ __launch_bounds__(256) void deconv2_kernel(
    const float* __restrict__ in, const float* __restrict__ w,
    const float* __restrict__ bias, float* __restrict__ out,
    int N, int Hin, int Win, int Hout, int Wout)
{
    constexpr int RP = 4, NC = 4;
    constexpr int CQ = CO / NC;
    constexpr int G  = 256 / CQ;

    const int cq = threadIdx.x % CQ;
    const int g  = threadIdx.x / CQ;
    const int w0 = (blockIdx.x * G + g) * RP;
    const int h0 = blockIdx.y * 2;
    const int n  = blockIdx.z;
    if (w0 >= Wout) return;

    const int  iwb  = w0 >> 1;
    const bool left = (iwb >= 1);
    const int  ihyA = (h0 >> 1) - 1;
    const int  ihyB = (h0 >> 1);

    u64 acc_e[RP][2], acc_o[RP][2];
    #pragma unroll
    for (int r=0;r<RP;r++){
        acc_e[r][0]=0ull; acc_e[r][1]=0ull;
        acc_o[r][0]=0ull; acc_o[r][1]=0ull;
    }

    // apply taps of one ky-row of weights to an accumulator pair set
    auto apply_ky = [&](u64 (&acc)[RP][2], const float* __restrict__ wky,
                        const u64* pm1, const u64* p0, const u64* pp1){
        #pragma unroll
        for (int c=0;c<4;c++){
            ulonglong2 wv0 = *reinterpret_cast<const ulonglong2*>(wky + (size_t)c*CO);
            ulonglong2 wv1 = *reinterpret_cast<const ulonglong2*>(wky + (size_t)(CI + c)*CO);
            ulonglong2 wv2 = *reinterpret_cast<const ulonglong2*>(wky + (size_t)(2*CI + c)*CO);
            ffma2(acc[0][0], wv0.x, pm1[c]); ffma2(acc[0][1], wv0.y, pm1[c]);
            ffma2(acc[0][0], wv2.x, p0[c]);  ffma2(acc[0][1], wv2.y, p0[c]);
            ffma2(acc[1][0], wv1.x, p0[c]);  ffma2(acc[1][1], wv1.y, p0[c]);
            ffma2(acc[2][0], wv0.x, p0[c]);  ffma2(acc[2][1], wv0.y, p0[c]);
            ffma2(acc[2][0], wv2.x, pp1[c]); ffma2(acc[2][1], wv2.y, pp1[c]);
            ffma2(acc[3][0], wv1.x, pp1[c]); ffma2(acc[3][1], wv1.y, pp1[c]);
        }
    };

    // ---- phase A: input row ihyA -> even output row via ky=0 ----
    if (ihyA >= 0){
        const float* __restrict__ rowp = in + (size_t)(n*Hin + ihyA) * Win * CI;
        #pragma unroll 2
        for (int ci=0; ci<CI; ci+=4){
            u64 pm1[4], p0[4], pp1[4];
            if (left){
                float4 xm = *reinterpret_cast<const float4*>(rowp + (size_t)(iwb-1)*CI + ci);
                pm1[0]=pack2(xm.x); pm1[1]=pack2(xm.y); pm1[2]=pack2(xm.z); pm1[3]=pack2(xm.w);
            } else { pm1[0]=pm1[1]=pm1[2]=pm1[3]=0ull; }
            float4 x0 = *reinterpret_cast<const float4*>(rowp + (size_t)iwb*CI + ci);
            float4 xp = *reinterpret_cast<const float4*>(rowp + (size_t)(iwb+1)*CI + ci);
            p0[0]=pack2(x0.x); p0[1]=pack2(x0.y); p0[2]=pack2(x0.z); p0[3]=pack2(x0.w);
            pp1[0]=pack2(xp.x); pp1[1]=pack2(xp.y); pp1[2]=pack2(xp.z); pp1[3]=pack2(xp.w);
            apply_ky(acc_e, w + (size_t)(0*3*CI + ci)*CO + NC*cq, pm1, p0, pp1);
        }
    }

    // ---- phase B: input row ihyB -> even row via ky=2, odd row via ky=1 ----
    {
        const float* __restrict__ rowp = in + (size_t)(n*Hin + ihyB) * Win * CI;
        #pragma unroll 2
        for (int ci=0; ci<CI; ci+=4){
            u64 pm1[4], p0[4], pp1[4];
            if (left){
                float4 xm = *reinterpret_cast<const float4*>(rowp + (size_t)(iwb-1)*CI + ci);
                pm1[0]=pack2(xm.x); pm1[1]=pack2(xm.y); pm1[2]=pack2(xm.z); pm1[3]=pack2(xm.w);
            } else { pm1[0]=pm1[1]=pm1[2]=pm1[3]=0ull; }
            float4 x0 = *reinterpret_cast<const float4*>(rowp + (size_t)iwb*CI + ci);
            float4 xp = *reinterpret_cast<const float4*>(rowp + (size_t)(iwb+1)*CI + ci);
            p0[0]=pack2(x0.x); p0[1]=pack2(x0.y); p0[2]=pack2(x0.z); p0[3]=pack2(x0.w);
            pp1[0]=pack2(xp.x); pp1[1]=pack2(xp.y); pp1[2]=pack2(xp.z); pp1[3]=pack2(xp.w);
            apply_ky(acc_e, w + (size_t)(2*3*CI + ci)*CO + NC*cq, pm1, p0, pp1);
            apply_ky(acc_o, w + (size_t)(1*3*CI + ci)*CO + NC*cq, pm1, p0, pp1);
        }
    }

    const float4 bv = *reinterpret_cast<const float4*>(bias + NC*cq);
    #pragma unroll
    for (int row=0; row<2; row++){
        u64 (&acc)[RP][2] = row ? acc_o : acc_e;
        const size_t ob = ((size_t)(n*Hout + h0 + row)*Wout + w0)*CO + NC*cq;
        #pragma unroll
        for (int r=0;r<RP;r++){
            float a0,a1,a2,a3;
            unpack2(a0,a1,acc[r][0]); unpack2(a2,a3,acc[r][1]);
            a0 += bv.x; a1 += bv.y; a2 += bv.z; a3 += bv.w;
            a0 = (a0 > 0.f) ? a0 : LRELU_ALPHA * a0;
            a1 = (a1 > 0.f) ? a1 : LRELU_ALPHA * a1;
            a2 = (a2 > 0.f) ? a2 : LRELU_ALPHA * a2;
            a3 = (a3 > 0.f) ? a3 : LRELU_ALPHA * a3;
            float4 o; o.x=a0; o.y=a1; o.z=a2; o.w=a3;
            *reinterpret_cast<float4*>(out + ob + (size_t)r*CO) = o;
        }
    }
}

// ---------------------------------------------------------------------------
// R3 conv kernel (encoder): stride-2 SAME conv (pad_lo=0), thread = 4 couts x RP cols
// ---------------------------------------------------------------------------
template<int S, int DIL, int PAD, int CI, int CO, int RP, bool RELU>
__global__ __launch_bounds__(256) void conv4_kernel(
    const float* __restrict__ in, const float* __restrict__ w,
    const float* __restrict__ bias, float* __restrict__ out,
    int N, int Hin, int Win, int Hout, int Wout)
{
    constexpr int CQ = CO / 4;
    constexpr int G  = 256 / CQ;
    static_assert(RP % 2 == 0, "RP even");

    const int cq = threadIdx.x % CQ;
    const int g  = threadIdx.x / CQ;
    const int w0 = (blockIdx.x * G + g) * RP;
    const int h  = blockIdx.y;
    const int n  = blockIdx.z;
    if (w0 >= Wout) return;

    u64 acc0[RP], acc1[RP];
    #pragma unroll
    for (int r=0;r<RP;r++){ acc0[r]=0ull; acc1[r]=0ull; }

    #pragma unroll
    for (int ky=0; ky<3; ky++){
        int uy = h*S + ky - PAD;
        int ihy;
        if (DIL==2){ if (uy & 1) continue; ihy = uy >> 1; } else { ihy = uy; }
        if (ihy < 0 || ihy >= Hin) continue;
        const float* __restrict__ rowp = in + (size_t)(n*Hin + ihy) * Win * CI;

        #pragma unroll
        for (int kx=0; kx<3; kx++){
            const float* __restrict__ wp = w + (size_t)((ky*3+kx)*CI) * CO + 4*cq;
            int  ofs[RP];
            bool v[RP];
            #pragma unroll
            for (int r=0;r<RP;r++){
                bool phase = (DIL==1) || (((r + kx - PAD) & 1) == 0);
                int ux = (w0+r)*S + kx - PAD;
                int iw = (DIL==2) ? (ux >> 1) : ux;
                v[r]   = phase && (iw >= 0) && (iw < Win);
                ofs[r] = v[r] ? iw*CI : 0;
            }

            if constexpr (CI % 4 == 0) {
                #pragma unroll 2
                for (int ci=0; ci<CI; ci+=4){
                    ulonglong2 wv0 = *reinterpret_cast<const ulonglong2*>(wp + (size_t)(ci+0)*CO);
                    ulonglong2 wv1 = *reinterpret_cast<const ulonglong2*>(wp + (size_t)(ci+1)*CO);
                    ulonglong2 wv2 = *reinterpret_cast<const ulonglong2*>(wp + (size_t)(ci+2)*CO);
                    ulonglong2 wv3 = *reinterpret_cast<const ulonglong2*>(wp + (size_t)(ci+3)*CO);
                    #pragma unroll
                    for (int r=0;r<RP;r++){
                        if ((DIL==1) || (((r + kx - PAD) & 1) == 0)){
                            if (v[r]){
                                float4 xv = *reinterpret_cast<const float4*>(rowp + ofs[r] + ci);
                                u64 p0 = pack2(xv.x), p1 = pack2(xv.y);
                                u64 p2 = pack2(xv.z), p3 = pack2(xv.w);
                                ffma2(acc0[r], wv0.x, p0); ffma2(acc1[r], wv0.y, p0);
                                ffma2(acc0[r], wv1.x, p1); ffma2(acc1[r], wv1.y, p1);
                                ffma2(acc0[r], wv2.x, p2); ffma2(acc1[r], wv2.y, p2);
                                ffma2(acc0[r], wv3.x, p3); ffma2(acc1[r], wv3.y, p3);
                            }
                        }
                    }
                }
            } else {
                #pragma unroll
                for (int ci=0; ci<CI; ci++){
                    ulonglong2 wv = *reinterpret_cast<const ulonglong2*>(wp + (size_t)ci*CO);
                    #pragma unroll
                    for (int r=0;r<RP;r++){
                        if (v[r]){
                            u64 p = pack2(rowp[ofs[r] + ci]);
                            ffma2(acc0[r], wv.x, p);
                            ffma2(acc1[r], wv.y, p);
                        }
                    }
                }
            }
        }
    }

    const float4 bv = *reinterpret_cast<const float4*>(bias + 4*cq);
    const size_t ob = ((size_t)(n*Hout + h)*Wout + w0)*CO + 4*cq;
    #pragma unroll
    for (int r=0;r<RP;r++){
        float a0,a1,a2,a3;
        unpack2(a0,a1,acc0[r]); unpack2(a2,a3,acc1[r]);
        a0 += bv.x; a1 += bv.y; a2 += bv.z; a3 += bv.w;
        if (RELU){
            a0 = (a0 > 0.f) ? a0 : LRELU_ALPHA * a0;
            a1 = (a1 > 0.f) ? a1 : LRELU_ALPHA * a1;
            a2 = (a2 > 0.f) ? a2 : LRELU_ALPHA * a2;
            a3 = (a3 > 0.f) ? a3 : LRELU_ALPHA * a3;
        }
        float4 o; o.x=a0; o.y=a1; o.z=a2; o.w=a3;
        *reinterpret_cast<float4*>(out + ob + (size_t)r*CO) = o;
    }
}

// ---------------------------------------------------------------------------
// fused enc4 (1x1 conv, 64->32) + vector quantization; 64-thr blocks for spread
// ---------------------------------------------------------------------------
__global__ __launch_bounds__(64) void enc4_vq_kernel(
    const float* __restrict__ h3, const float* __restrict__ w,
    const float* __restrict__ b, const float* __restrict__ cb,
    float* __restrict__ q, int NP)
{
    __shared__ float sw[2048];   // w  [64][32]
    __shared__ float scb[2048];  // cb [32][64]
    for (int i = threadIdx.x; i < 2048; i += 64){ sw[i] = w[i]; scb[i] = cb[i]; }
    __syncthreads();

    int p = blockIdx.x*blockDim.x + threadIdx.x;
    if (p >= NP) return;
    float z[32];
    #pragma unroll
    for (int d=0;d<32;d++) z[d] = b[d];
    const float* hp = h3 + (size_t)p*64;
    #pragma unroll
    for (int c4=0;c4<64;c4+=4){
        float4 hv = *reinterpret_cast<const float4*>(hp + c4);
        #pragma unroll
        for (int d=0;d<32;d++){
            z[d] += hv.x * sw[(c4+0)*32 + d];
            z[d] += hv.y * sw[(c4+1)*32 + d];
            z[d] += hv.z * sw[(c4+2)*32 + d];
            z[d] += hv.w * sw[(c4+3)*32 + d];
        }
    }
    float best = 3.4e38f; int bk = 0;
    for (int k=0;k<64;k++){
        float dist = 0.f;
        #pragma unroll
        for (int d=0;d<32;d++){
            float e = scb[d*64 + k];
            dist += e*(e - 2.f*z[d]);
        }
        if (dist < best){ best = dist; bk = k; }   // strict < == first-min (jnp.argmin)
    }
    float* qp = q + (size_t)p*32;
    #pragma unroll
    for (int d=0;d<32;d++) qp[d] = scb[d*64 + bk];
}

// ---------------------------------------------------------------------------
// dec4: conv_transpose stride 1 (== SAME conv pad 1), CI=32, CO=1.
// ---------------------------------------------------------------------------
__global__ __launch_bounds__(256) void dec4_kernel(
    const float* __restrict__ in, const float* __restrict__ w,
    const float* __restrict__ b, float* __restrict__ out,
    int N, int H, int W)
{
    int gw = (blockIdx.x * blockDim.x + threadIdx.x) >> 5;
    int lane = threadIdx.x & 31;
    int gpr = W >> 2;
    int total = N*H*gpr;
    if (gw >= total) return;
    int gx = gw % gpr; int t = gw / gpr;
    int h = t % H; int n = t / H;
    int w0 = gx*4;

    float wk[9];
    #pragma unroll
    for (int i=0;i<9;i++) wk[i] = w[i*32 + lane];

    float acc[4] = {0.f,0.f,0.f,0.f};
    #pragma unroll
    for (int ky=0;ky<3;ky++){
        int ih = h + ky - 1;
        if (ih < 0 || ih >= H) continue;
        const float* rowp = in + ((size_t)(n*H + ih)*W)*32 + lane;
        float v[6];
        #pragma unroll
        for (int c=0;c<6;c++){
            int iw = w0 - 1 + c;
            v[c] = (iw >= 0 && iw < W) ? rowp[(size_t)iw*32] : 0.f;
        }
        #pragma unroll
        for (int kx=0;kx<3;kx++)
            #pragma unroll
            for (int r=0;r<4;r++)
                acc[r] += v[r+kx] * wk[ky*3+kx];
    }
    float bv = b[0];
    #pragma unroll
    for (int r=0;r<4;r++){
        float a = acc[r];
        #pragma unroll
        for (int o=16;o;o>>=1) a += __shfl_xor_sync(0xffffffffu, a, o);
        if (lane == 0) out[((size_t)(n*H + h)*W) + w0 + r] = a + bv;
    }
}

extern "C" void kernel_launch(void* const* d_in, const int* in_sizes, int n_in,
                              void* d_out, int out_size)
{
    (void)in_sizes; (void)n_in; (void)out_size;
    const float* x   = (const float*)d_in[0];
    const float* e1w = (const float*)d_in[1];  const float* e1b = (const float*)d_in[2];
    const float* e2w = (const float*)d_in[3];  const float* e2b = (const float*)d_in[4];
    const float* e3w = (const float*)d_in[5];  const float* e3b = (const float*)d_in[6];
    const float* e4w = (const float*)d_in[7];  const float* e4b = (const float*)d_in[8];
    const float* cb  = (const float*)d_in[9];
    const float* d1w = (const float*)d_in[10]; const float* d1b = (const float*)d_in[11];
    const float* d2w = (const float*)d_in[12]; const float* d2b = (const float*)d_in[13];
    const float* d3w = (const float*)d_in[14]; const float* d3b = (const float*)d_in[15];
    const float* d4w = (const float*)d_in[16]; const float* d4b = (const float*)d_in[17];
    float* out = (float*)d_out;

    float *A, *B;
    cudaGetSymbolAddress((void**)&A, g_bufA);
    cudaGetSymbolAddress((void**)&B, g_bufB);

    // encoder: 256 -> 128 -> 64 -> 32   (R3 configs)
    conv4_kernel<2,1,0, 3,32,4,true ><<< dim3(1,128,32), 256 >>>(x, e1w, e1b, A, 32,256,256,128,128);
    conv4_kernel<2,1,0,32,64,4,true ><<< dim3(1, 64,32), 256 >>>(A, e2w, e2b, B, 32,128,128, 64, 64);
    conv4_kernel<2,1,0,64,64,2,true ><<< dim3(1, 32,32), 256 >>>(B, e3w, e3b, A, 32, 64, 64, 32, 32);

    // enc4 (1x1) + VQ fused
    enc4_vq_kernel<<< 512, 64 >>>(A, e4w, e4b, cb, B, 32768);

    // decoder: 32 -> 64 -> 128 -> 256  (row-paired deconv)
    // dec1: CO=64 -> CQ=16, G=16 -> 64 cols; rows 64/2=32
    deconv2_kernel<32,64><<< dim3(1, 32,32), 256 >>>(B, d1w, d1b, A, 32, 32, 32, 64, 64);
    // dec2: CO=64 -> CQ=16, G=16 -> 64 cols x2 blocks = 128; rows 128/2=64
    deconv2_kernel<64,64><<< dim3(2, 64,32), 256 >>>(A, d2w, d2b, B, 32, 64, 64,128,128);
    // dec3: CO=32 -> CQ=8, G=32 -> 128 cols x2 = 256; rows 256/2=128
    deconv2_kernel<64,32><<< dim3(2,128,32), 256 >>>(B, d3w, d3b, A, 32,128,128,256,256);

    // dec4: stride-1 deconv == SAME conv, CO=1
    dec4_kernel<<< 65536, 256 >>>(A, d4w, d4b, out, 32, 256, 256);
}